// round 17
// baseline (speedup 1.0000x reference)
#include <cuda_runtime.h>
#include <cuda_bf16.h>
#include <cuda_fp16.h>
#include <math.h>
#include <stdint.h>

#define BATCH   32768
#define D_IN    512
#define D_DENSE 256
#define TSTEPS  16
#define FEAT    16
#define H1      128
#define H2      32
#define NCLS    10

// ---------------- state: COLUMN-major [feature][BATCH], single fp16 ----------------
__device__ __half g_act[D_DENSE * BATCH];
__device__ __half g_h1[2][H1 * BATCH];
__device__ __half g_h2[2][H2 * BATCH];
__device__ float g_c1[H1 * BATCH], g_c2[H2 * BATCH];

// prepacked weights: single fp16
__device__ __half g_Wp1[(4 * H1) * (FEAT + H1)];   // [512][144] gate-interleaved
__device__ __half g_Wp2[(4 * H2) * (H1 + H2)];     // [128][160]
__device__ __half g_WpD[D_DENSE * D_IN];           // [256][512]
__device__ float g_bc1[4 * H1], g_bc2[4 * H2];
__device__ float g_d1sc[D_DENSE], g_d1sh[D_DENSE];

// ---------------- helpers ----------------
__device__ __forceinline__ uint32_t smem_u32(const void* p) {
    uint32_t a;
    asm("{ .reg .u64 t; cvta.to.shared.u64 t, %1; cvt.u32.u64 %0, t; }" : "=r"(a) : "l"(p));
    return a;
}
__device__ __forceinline__ float ftanh(float x) {
    float y;
    asm("tanh.approx.f32 %0, %1;" : "=f"(y) : "f"(x));
    return y;
}
__device__ __forceinline__ float fsigm(float x) { return 0.5f * ftanh(0.5f * x) + 0.5f; }

__device__ __forceinline__ void ldsm4(uint32_t* r, uint32_t addr) {
    asm volatile("ldmatrix.sync.aligned.m8n8.x4.shared.b16 {%0,%1,%2,%3}, [%4];"
                 : "=r"(r[0]), "=r"(r[1]), "=r"(r[2]), "=r"(r[3]) : "r"(addr));
}
__device__ __forceinline__ void ldsm4t(uint32_t* r, uint32_t addr) {
    asm volatile("ldmatrix.sync.aligned.m8n8.x4.trans.shared.b16 {%0,%1,%2,%3}, [%4];"
                 : "=r"(r[0]), "=r"(r[1]), "=r"(r[2]), "=r"(r[3]) : "r"(addr));
}
__device__ __forceinline__ void mma16816h(float* d, const uint32_t* a, uint32_t b0, uint32_t b1) {
    asm volatile(
        "mma.sync.aligned.m16n8k16.row.col.f32.f16.f16.f32 "
        "{%0,%1,%2,%3}, {%4,%5,%6,%7}, {%8,%9}, {%0,%1,%2,%3};"
        : "+f"(d[0]), "+f"(d[1]), "+f"(d[2]), "+f"(d[3])
        : "r"(a[0]), "r"(a[1]), "r"(a[2]), "r"(a[3]), "r"(b0), "r"(b1));
}
__device__ __forceinline__ void cp16(uint32_t dst, const void* src) {
    asm volatile("cp.async.cg.shared.global [%0], [%1], 16;" :: "r"(dst), "l"(src));
}
#define CP_COMMIT() asm volatile("cp.async.commit_group;" ::: "memory")
#define CP_WAIT(n)  asm volatile("cp.async.wait_group %0;" :: "n"(n) : "memory")

// ===== fused LSTM step: M=256/CTA, resident full-K B, pipelined A/c subtiles =====
// 512 threads, 16 warps 4Mx4N, warp tile 32x32, subtile 128x128, 2 subtiles.
#define SROW 136
#define ASTG (80 * SROW * 2)         // 21760 per A stage (max chunk 80 k-rows)
#define BOFF (2 * ASTG)              // 43520
#define CROW 132
#define CSZ  (32 * CROW * 4)         // 16896
#define SM_STEP (BOFF + 128 * (160 + 8) * 2 + CSZ)   // 103424 (K=160 case)

template <int NKK, int SB>
__device__ __forceinline__ void gemm_chunk(uint32_t As, uint32_t Bs, int kbase,
                                           uint32_t arow, uint32_t acol,
                                           uint32_t brow, uint32_t bcol8,
                                           float acc[2][4][4]) {
#pragma unroll
    for (int kk = 0; kk < NKK; kk++) {
        uint32_t a0[4], a1[4];
        const uint32_t hr = (uint32_t)(kk * 16) + arow;
        ldsm4t(a0, As + (hr * SROW + acol) * 2);
        ldsm4t(a1, As + (hr * SROW + acol + 16) * 2);
        const uint32_t cofs = (uint32_t)(kbase + kk * 16) + bcol8;
#pragma unroll
        for (int nj = 0; nj < 2; nj++) {
            uint32_t b[4];
            ldsm4(b, Bs + ((brow + nj * 16) * SB + cofs) * 2);
            mma16816h(acc[0][2 * nj], a0, b[0], b[1]);
            mma16816h(acc[0][2 * nj + 1], a0, b[2], b[3]);
            mma16816h(acc[1][2 * nj], a1, b[0], b[1]);
            mma16816h(acc[1][2 * nj + 1], a1, b[2], b[3]);
        }
    }
}

template <int KX, int HID>
__device__ __forceinline__ void lstm_body(int t, int m0, int n0, char* smemc) {
    constexpr int K = KX + HID;
    constexpr int BK0 = 80, BK1 = K - BK0;
    constexpr int SB = K + 8;
    constexpr int COFF = BOFF + 128 * SB * 2;
    const int tid = threadIdx.x;
    const int lane = tid & 31, wid = tid >> 5;
    const int wm = wid & 3, wn = wid >> 2;    // 4 x 4
    const uint32_t sbase = smem_u32(smemc);
    const int p = t & 1;

    const __half *xsrc, *hsrc;
    __half* hdst;
    float* cbuf;
    const __half* W;
    const float* bias;
    int xoff;
    if (HID == H1) {
        xsrc = g_act; xoff = t * FEAT;
        hsrc = g_h1[p]; hdst = g_h1[p ^ 1];
        cbuf = g_c1; W = g_Wp1; bias = g_bc1;
    } else {
        xsrc = g_h1[p ^ 1]; xoff = 0;
        hsrc = g_h2[p]; hdst = g_h2[p ^ 1];
        cbuf = g_c2; W = g_Wp2; bias = g_bc2;
    }
    const int u0 = n0 >> 2;

    auto load_a = [&](int sub, int chunk) {
        const int kbase = chunk ? BK0 : 0;
        const int bk = chunk ? BK1 : BK0;
        const int m0s = m0 + sub * 128;
        const uint32_t As = sbase + (chunk ? ASTG : 0);
        for (int task = tid; task < bk * 16; task += 512) {
            const int k = task >> 4, mg = task & 15;
            const int col = kbase + k;
            const __half* src = (col < KX)
                ? xsrc + (size_t)(xoff + col) * BATCH + m0s + mg * 8
                : hsrc + (size_t)(col - KX) * BATCH + m0s + mg * 8;
            cp16(As + (uint32_t)(k * SROW + mg * 8) * 2, src);
        }
    };
    auto load_c = [&](int sub) {
        const int m0s = m0 + sub * 128;
        for (int task = tid; task < 32 * 32; task += 512) {
            const int ul = task >> 5, gg = task & 31;
            cp16(sbase + COFF + (uint32_t)(ul * CROW + gg * 4) * 4,
                 cbuf + (size_t)(u0 + ul) * BATCH + m0s + gg * 4);
        }
    };

    // g0: resident full-K B
    for (int task = tid; task < 128 * (K / 8); task += 512) {
        const int n = task / (K / 8), gg = task % (K / 8);
        cp16(sbase + BOFF + (uint32_t)(n * SB + gg * 8) * 2,
             W + (size_t)(n0 + n) * K + gg * 8);
    }
    CP_COMMIT();
    load_a(0, 0); CP_COMMIT();               // g1
    load_a(0, 1); load_c(0); CP_COMMIT();    // g2

    const uint32_t arow = (uint32_t)((lane & 7) + ((lane >> 4) << 3));
    const uint32_t acol = (uint32_t)(wm * 32 + (((lane >> 3) & 1) << 3));
    const uint32_t brow = (uint32_t)(wn * 32 + ((lane >> 4) << 3) + (lane & 7));
    const uint32_t bcol8 = (uint32_t)(((lane >> 3) & 1) << 3);
    float acc[2][4][4] = {};

    const float* const cs = (const float*)(smemc + COFF);
    const int g = lane >> 2;
    const bool odd = lane & 1;
    auto epilogue = [&](int sub) {
        const int m0s = m0 + sub * 128;
#pragma unroll
        for (int ni = 0; ni < 4; ni++) {
            const int ul = wn * 8 + ni * 2 + ((lane & 2) >> 1);
            const int u = u0 + ul;
            const float4 bb = *(const float4*)(bias + 4 * u);
#pragma unroll
            for (int mi = 0; mi < 2; mi++) {
                const float d0 = acc[mi][ni][0], d1 = acc[mi][ni][1];
                const float d2 = acc[mi][ni][2], d3 = acc[mi][ni][3];
                const float s0 = __shfl_xor_sync(0xffffffffu, odd ? d0 : d2, 1);
                const float s1 = __shfl_xor_sync(0xffffffffu, odd ? d1 : d3, 1);
                const float zi = (odd ? s0 : d0) + bb.x;
                const float zf = (odd ? s1 : d1) + bb.y;
                const float zg = (odd ? d2 : s0) + bb.z;
                const float zo = (odd ? d3 : s1) + bb.w;
                const int rl = wm * 32 + mi * 16 + g + (odd ? 8 : 0);
                const float ig = fsigm(zi);
                const float fg = fsigm(zf);
                const float gg = ftanh(zg);
                const float og = fsigm(zo);
                const float cn = fg * cs[ul * CROW + rl] + ig * gg;
                const size_t off = (size_t)u * BATCH + m0s + rl;
                cbuf[off] = cn;
                hdst[off] = __float2half_rn(og * ftanh(cn));
            }
        }
    };

    // ---- subtile 0 ----
    CP_WAIT(1); __syncthreads();                      // B + A00 ready
    gemm_chunk<BK0 / 16, SB>(sbase, sbase + BOFF, 0, arow, acol, brow, bcol8, acc);
    __syncthreads();                                  // stage0 reads done
    load_a(1, 0); CP_COMMIT();                        // g3 -> stage0
    CP_WAIT(1); __syncthreads();                      // g2 (A01 + c0) ready
    gemm_chunk<BK1 / 16, SB>(sbase + ASTG, sbase + BOFF, BK0, arow, acol, brow, bcol8, acc);
    epilogue(0);
    __syncthreads();                                  // stage1 + C reads done
    load_a(1, 1); load_c(1); CP_COMMIT();             // g4 -> stage1, C
    // ---- subtile 1 ----
#pragma unroll
    for (int a = 0; a < 2; a++)
#pragma unroll
        for (int b = 0; b < 4; b++)
#pragma unroll
            for (int c = 0; c < 4; c++) acc[a][b][c] = 0.f;
    CP_WAIT(1); __syncthreads();                      // g3 (A10) ready
    gemm_chunk<BK0 / 16, SB>(sbase, sbase + BOFF, 0, arow, acol, brow, bcol8, acc);
    CP_WAIT(0); __syncthreads();                      // g4 (A11 + c1) ready
    gemm_chunk<BK1 / 16, SB>(sbase + ASTG, sbase + BOFF, BK0, arow, acol, brow, bcol8, acc);
    epilogue(1);
}

__global__ __launch_bounds__(512, 2) void lstm1_first_kernel() {
    extern __shared__ char smem[];
    lstm_body<FEAT, H1>(0, (blockIdx.x & 127) * 256, (blockIdx.x >> 7) * 128, smem);
}

// combined: lstm2(t) on blocks [0,128); lstm1(t+1) on blocks [128,640)
__global__ __launch_bounds__(512, 2) void step_kernel(int t, int do_l1) {
    extern __shared__ char smem[];
    if (blockIdx.x < 128) {
        lstm_body<H1, H2>(t, blockIdx.x * 256, 0, smem);
    } else if (do_l1) {
        const int bx = blockIdx.x - 128;
        lstm_body<FEAT, H1>(t + 1, (bx & 127) * 256, (bx >> 7) * 128, smem);
    }
}

// ---------------- init & prepack ----------------
__global__ void init_state_kernel() {
    int idx = blockIdx.x * blockDim.x + threadIdx.x;
    int stride = gridDim.x * blockDim.x;
    const __half z = __float2half(0.f);
    for (int i = idx; i < BATCH * H1; i += stride) { g_h1[0][i] = z; g_c1[i] = 0.f; }
    for (int i = idx; i < BATCH * H2; i += stride) { g_h2[0][i] = z; g_c2[i] = 0.f; }
}

__global__ void prepack_kernel(const float* __restrict__ Wx1, const float* __restrict__ Wh1,
                               const float* __restrict__ b1,
                               const float* __restrict__ Wx2, const float* __restrict__ Wh2,
                               const float* __restrict__ b2,
                               const float* __restrict__ W_d1, const float* __restrict__ b_d1,
                               const float* __restrict__ gamma, const float* __restrict__ beta,
                               const float* __restrict__ mean, const float* __restrict__ var) {
    int idx = blockIdx.x * blockDim.x + threadIdx.x;
    int stride = gridDim.x * blockDim.x;
    {
        constexpr int K = FEAT + H1;
        for (int i = idx; i < 4 * H1 * K; i += stride) {
            int n = i / K, k = i % K;
            int u = n >> 2, g = n & 3, src = g * H1 + u;
            float w = (k < FEAT) ? Wx1[k * 4 * H1 + src] : Wh1[(k - FEAT) * 4 * H1 + src];
            g_Wp1[(size_t)n * K + k] = __float2half_rn(w);
        }
        for (int i = idx; i < 4 * H1; i += stride) {
            int u = i >> 2, g = i & 3;
            g_bc1[i] = b1[g * H1 + u];
        }
    }
    {
        constexpr int K = H1 + H2;
        for (int i = idx; i < 4 * H2 * K; i += stride) {
            int n = i / K, k = i % K;
            int u = n >> 2, g = n & 3, src = g * H2 + u;
            float w = (k < H1) ? Wx2[k * 4 * H2 + src] : Wh2[(k - H1) * 4 * H2 + src];
            g_Wp2[(size_t)n * K + k] = __float2half_rn(w);
        }
        for (int i = idx; i < 4 * H2; i += stride) {
            int u = i >> 2, g = i & 3;
            g_bc2[i] = b2[g * H2 + u];
        }
    }
    for (int i = idx; i < D_DENSE * D_IN; i += stride) {
        int n = i / D_IN, k = i % D_IN;
        g_WpD[(size_t)n * D_IN + k] = __float2half_rn(W_d1[(size_t)k * D_DENSE + n]);
    }
    for (int i = idx; i < D_DENSE; i += stride) {
        float sc = gamma[i] * rsqrtf(var[i] + 1e-3f);
        g_d1sc[i] = sc;
        g_d1sh[i] = beta[i] + (b_d1[i] - mean[i]) * sc;
    }
}

// ---------------- Dense1 (R15 verified): single fp16, 512 thr 4Mx4N ----------------
#define D1S 136
#define D1_ASZ (128 * D1S * 2)
#define SMD (2 * D1_ASZ)   // 69632

__global__ __launch_bounds__(512, 2) void dense1_kernel(const float* __restrict__ x) {
    constexpr int KP = 128;
    extern __shared__ char smem[];
    const uint32_t Asm = smem_u32(smem);
    const uint32_t Bsm = Asm + D1_ASZ;
    const int tid = threadIdx.x;
    const int lane = tid & 31, wid = tid >> 5;
    const int wm = wid & 3, wn = wid >> 2;
    const int m0 = blockIdx.x * 128, n0 = blockIdx.y * 128;

    const uint32_t abase = Asm + ((((uint32_t)(wm * 32 + (lane & 15))) * D1S + ((lane >> 4) << 3)) << 1);
    const uint32_t brow = (uint32_t)(wn * 32 + ((lane >> 4) << 3) + (lane & 7));
    const uint32_t bcol8 = (uint32_t)(((lane >> 3) & 1) << 3);

    float acc[2][4][4] = {};
    for (int p = 0; p < 4; p++) {
        for (int task = tid; task < 128 * 16; task += 512) {
            const int r = task >> 4, o = task & 15;
            const float* src = x + (size_t)(m0 + r) * D_IN + p * KP + o * 8;
            const float4 v0 = *(const float4*)src;
            const float4 v1 = *(const float4*)(src + 4);
            __half h[8];
            h[0] = __float2half_rn(v0.x); h[1] = __float2half_rn(v0.y);
            h[2] = __float2half_rn(v0.z); h[3] = __float2half_rn(v0.w);
            h[4] = __float2half_rn(v1.x); h[5] = __float2half_rn(v1.y);
            h[6] = __float2half_rn(v1.z); h[7] = __float2half_rn(v1.w);
            *(uint4*)(smem + ((size_t)r * D1S + o * 8) * 2) = *(uint4*)h;
        }
        for (int task = tid; task < 128 * 16; task += 512) {
            const int n = task >> 4, gg = task & 15;
            cp16(Bsm + (uint32_t)(n * D1S + gg * 8) * 2,
                 g_WpD + (size_t)(n0 + n) * D_IN + p * KP + gg * 8);
        }
        CP_COMMIT();
        CP_WAIT(0);
        __syncthreads();
#pragma unroll
        for (int kk = 0; kk < KP / 16; kk++) {
            uint32_t a0[4], a1[4];
            ldsm4(a0, abase + (kk * 16) * 2);
            ldsm4(a1, abase + (16 * D1S + kk * 16) * 2);
            const uint32_t cofs = (uint32_t)(kk * 16) + bcol8;
#pragma unroll
            for (int nj = 0; nj < 2; nj++) {
                uint32_t b[4];
                ldsm4(b, Bsm + ((brow + nj * 16) * D1S + cofs) * 2);
                mma16816h(acc[0][2 * nj], a0, b[0], b[1]);
                mma16816h(acc[0][2 * nj + 1], a0, b[2], b[3]);
                mma16816h(acc[1][2 * nj], a1, b[0], b[1]);
                mma16816h(acc[1][2 * nj + 1], a1, b[2], b[3]);
            }
        }
        __syncthreads();
    }

    const int g = lane >> 2;
#pragma unroll
    for (int ni = 0; ni < 4; ni++) {
        const int n = n0 + wn * 32 + ni * 8 + (lane & 3) * 2;
        const float sc0 = g_d1sc[n], sc1 = g_d1sc[n + 1];
        const float sh0 = g_d1sh[n], sh1 = g_d1sh[n + 1];
#pragma unroll
        for (int mi = 0; mi < 2; mi++) {
#pragma unroll
            for (int half = 0; half < 2; half++) {
                const int row = m0 + wm * 32 + mi * 16 + g + half * 8;
                float v0 = acc[mi][ni][half * 2 + 0] * sc0 + sh0;
                float v1 = acc[mi][ni][half * 2 + 1] * sc1 + sh1;
                v0 = (v0 >= 0.f) ? v0 : 0.2f * v0;
                v1 = (v1 >= 0.f) ? v1 : 0.2f * v1;
                g_act[(size_t)n * BATCH + row] = __float2half_rn(v0);
                g_act[(size_t)(n + 1) * BATCH + row] = __float2half_rn(v1);
            }
        }
    }
}

// ---------------- Dense2 + softmax (col-major fp16 h2) ----------------
__global__ __launch_bounds__(256) void dense2_softmax_kernel(
    const float* __restrict__ Wd2, const float* __restrict__ bd2, float* __restrict__ out) {
    __shared__ float Ws[H2 * NCLS];
    __shared__ float bs[NCLS];
    int tid = threadIdx.x;
    for (int i = tid; i < H2 * NCLS; i += blockDim.x) Ws[i] = Wd2[i];
    if (tid < NCLS) bs[tid] = bd2[tid];
    __syncthreads();
    int row = blockIdx.x * blockDim.x + tid;
    const __half* hh = g_h2[0];  // t=15 writes buffer 0
    float acc[NCLS];
#pragma unroll
    for (int j = 0; j < NCLS; j++) acc[j] = bs[j];
#pragma unroll
    for (int k = 0; k < H2; k++) {
        float xv = __half2float(hh[(size_t)k * BATCH + row]);
#pragma unroll
        for (int j = 0; j < NCLS; j++) acc[j] += xv * Ws[k * NCLS + j];
    }
    float m = acc[0];
#pragma unroll
    for (int j = 1; j < NCLS; j++) m = fmaxf(m, acc[j]);
    float ssum = 0.f;
#pragma unroll
    for (int j = 0; j < NCLS; j++) { acc[j] = expf(acc[j] - m); ssum += acc[j]; }
    float inv = 1.f / ssum;
#pragma unroll
    for (int j = 0; j < NCLS; j++) out[(size_t)row * NCLS + j] = acc[j] * inv;
}

// ---------------- launch ----------------
extern "C" void kernel_launch(void* const* d_in, const int* in_sizes, int n_in,
                              void* d_out, int out_size) {
    const float* x        = (const float*)d_in[0];
    const float* W_d1     = (const float*)d_in[1];
    const float* b_d1     = (const float*)d_in[2];
    const float* bn_gamma = (const float*)d_in[3];
    const float* bn_beta  = (const float*)d_in[4];
    const float* bn_mean  = (const float*)d_in[5];
    const float* bn_var   = (const float*)d_in[6];
    const float* Wx1      = (const float*)d_in[7];
    const float* Wh1      = (const float*)d_in[8];
    const float* b1       = (const float*)d_in[9];
    const float* Wx2      = (const float*)d_in[10];
    const float* Wh2      = (const float*)d_in[11];
    const float* b2       = (const float*)d_in[12];
    const float* W_d2     = (const float*)d_in[13];
    const float* b_d2     = (const float*)d_in[14];
    float* out = (float*)d_out;

    cudaFuncSetAttribute(dense1_kernel, cudaFuncAttributeMaxDynamicSharedMemorySize, SMD);
    cudaFuncSetAttribute(lstm1_first_kernel, cudaFuncAttributeMaxDynamicSharedMemorySize, SM_STEP);
    cudaFuncSetAttribute(step_kernel, cudaFuncAttributeMaxDynamicSharedMemorySize, SM_STEP);

    prepack_kernel<<<256, 256>>>(Wx1, Wh1, b1, Wx2, Wh2, b2, W_d1, b_d1,
                                 bn_gamma, bn_beta, bn_mean, bn_var);
    init_state_kernel<<<2048, 256>>>();
    dense1_kernel<<<dim3(BATCH / 128, D_DENSE / 128), 512, SMD>>>(x);
    lstm1_first_kernel<<<512, 512, SM_STEP>>>();
    for (int t = 0; t < TSTEPS; t++) {
        step_kernel<<<640, 512, SM_STEP>>>(t, (t < TSTEPS - 1) ? 1 : 0);
    }
    dense2_softmax_kernel<<<BATCH / 256, 256>>>(W_d2, b_d2, out);
}